// round 5
// baseline (speedup 1.0000x reference)
#include <cuda_runtime.h>
#include <cuda_bf16.h>
#include <cstdint>
#include <cstddef>

#define T_SEQ 512
#define BATCH 64
#define NTOK  (BATCH * T_SEQ)   // 32768
#define NB 2                    // batches per GRU cluster

// ----------------------------- scratch ------------------------------------
__device__ float g_xw[(size_t)NTOK * 960];
__device__ float g_h1[(size_t)NTOK * 320];
__device__ float g_seq[(size_t)NTOK * 320];
__device__ float g_keys[(size_t)NTOK * 160];
__device__ float g_logits[(size_t)NTOK * 4];
__device__ float g_motion[NTOK];
__device__ float g_pooled[BATCH * 320];

// ----------------------- SGEMM: C = A(MxK) * B(NxK)^T + bias ---------------
// Ping-pong smem + register prefetch: one __syncthreads per K-tile.
#define BM 128
#define BN 128
#define BK 16

__global__ void __launch_bounds__(256) sgemm_bias(
    const float* __restrict__ A, const float* __restrict__ B,
    const float* __restrict__ bias, float* __restrict__ C,
    int M, int N, int K, int act)
{
    __shared__ float As[2][BK][BM + 4];
    __shared__ float Bs[2][BK][BN + 4];

    const int tid = threadIdx.x;
    const int tx = tid & 15;
    const int ty = tid >> 4;
    const int bm = blockIdx.y * BM;
    const int bn = blockIdx.x * BN;

    const int fr0 = (tid * 2) >> 2,     fc0 = (tid * 2) & 3;
    const int fr1 = (tid * 2 + 1) >> 2, fc1 = (tid * 2 + 1) & 3;

    float4 pa0, pa1, pb0, pb1;

    auto ldg_tile = [&](int kt) {
        const int k0 = kt * BK;
        pa0 = *reinterpret_cast<const float4*>(A + (size_t)(bm + fr0) * K + k0 + fc0 * 4);
        pa1 = *reinterpret_cast<const float4*>(A + (size_t)(bm + fr1) * K + k0 + fc1 * 4);
        pb0 = make_float4(0.f, 0.f, 0.f, 0.f);
        pb1 = make_float4(0.f, 0.f, 0.f, 0.f);
        if (bn + fr0 < N)
            pb0 = *reinterpret_cast<const float4*>(B + (size_t)(bn + fr0) * K + k0 + fc0 * 4);
        if (bn + fr1 < N)
            pb1 = *reinterpret_cast<const float4*>(B + (size_t)(bn + fr1) * K + k0 + fc1 * 4);
    };
    auto sts_tile = [&](int buf) {
        As[buf][fc0 * 4 + 0][fr0] = pa0.x; As[buf][fc0 * 4 + 1][fr0] = pa0.y;
        As[buf][fc0 * 4 + 2][fr0] = pa0.z; As[buf][fc0 * 4 + 3][fr0] = pa0.w;
        As[buf][fc1 * 4 + 0][fr1] = pa1.x; As[buf][fc1 * 4 + 1][fr1] = pa1.y;
        As[buf][fc1 * 4 + 2][fr1] = pa1.z; As[buf][fc1 * 4 + 3][fr1] = pa1.w;
        Bs[buf][fc0 * 4 + 0][fr0] = pb0.x; Bs[buf][fc0 * 4 + 1][fr0] = pb0.y;
        Bs[buf][fc0 * 4 + 2][fr0] = pb0.z; Bs[buf][fc0 * 4 + 3][fr0] = pb0.w;
        Bs[buf][fc1 * 4 + 0][fr1] = pb1.x; Bs[buf][fc1 * 4 + 1][fr1] = pb1.y;
        Bs[buf][fc1 * 4 + 2][fr1] = pb1.z; Bs[buf][fc1 * 4 + 3][fr1] = pb1.w;
    };

    float acc[8][8];
#pragma unroll
    for (int i = 0; i < 8; i++)
#pragma unroll
        for (int j = 0; j < 8; j++) acc[i][j] = 0.f;

    const int ntiles = K / BK;
    ldg_tile(0);
    sts_tile(0);
    __syncthreads();

    for (int kt = 0; kt < ntiles; kt++) {
        const int cur = kt & 1;
        if (kt + 1 < ntiles) ldg_tile(kt + 1);
#pragma unroll
        for (int kk = 0; kk < BK; kk++) {
            float4 a0 = *reinterpret_cast<const float4*>(&As[cur][kk][ty * 8]);
            float4 a1 = *reinterpret_cast<const float4*>(&As[cur][kk][ty * 8 + 4]);
            float4 b0 = *reinterpret_cast<const float4*>(&Bs[cur][kk][tx * 8]);
            float4 b1 = *reinterpret_cast<const float4*>(&Bs[cur][kk][tx * 8 + 4]);
            float av[8] = {a0.x, a0.y, a0.z, a0.w, a1.x, a1.y, a1.z, a1.w};
            float bv[8] = {b0.x, b0.y, b0.z, b0.w, b1.x, b1.y, b1.z, b1.w};
#pragma unroll
            for (int i = 0; i < 8; i++)
#pragma unroll
                for (int j = 0; j < 8; j++) acc[i][j] = fmaf(av[i], bv[j], acc[i][j]);
        }
        if (kt + 1 < ntiles) {
            sts_tile(cur ^ 1);
            __syncthreads();
        }
    }
#pragma unroll
    for (int i = 0; i < 8; i++) {
        size_t row = (size_t)(bm + ty * 8 + i);
#pragma unroll
        for (int j = 0; j < 8; j++) {
            int col = bn + tx * 8 + j;
            if (col < N) {
                float v = acc[i][j] + bias[col];
                if (act) v = tanhf(v);
                C[row * N + col] = v;
            }
        }
    }
}

// --------------------------- GRU layer (2-CTA cluster) ---------------------
// 128 CTAs = 64 clusters. cluster c = blockIdx.x>>1: dir = c&1, batch group
// = c>>1 (NB batches). rank = blockIdx.x&1 owns hidden units [rank*80,+80).
// Whh rows in REGISTERS. Per-step peer-h exchange via DSMEM stores + mbarrier
// handshake; the wait is hidden behind the local-half FMAs.
__device__ __forceinline__ void mbar_wait_acq(uint32_t mbar, uint32_t parity)
{
    asm volatile(
        "{\n\t.reg .pred P;\n\t"
        "WAITLP_%=:\n\t"
        "mbarrier.try_wait.parity.acquire.cluster.shared::cta.b64 P, [%0], %1, 0x989680;\n\t"
        "@P bra.uni WDONE_%=;\n\t"
        "bra.uni WAITLP_%=;\n\t"
        "WDONE_%=:\n\t}"
        :: "r"(mbar), "r"(parity) : "memory");
}

__global__ void __cluster_dims__(2, 1, 1) __launch_bounds__(256, 1) gru_layer(
    const float* __restrict__ xw,    // (NTOK, 960): col = dir*480 + gate*160 + unit
    const float* __restrict__ whh,   // (2, 480, 160)
    const float* __restrict__ bhh,   // (2, 480)
    float* __restrict__ out)         // (NTOK, 320): col = dir*160 + unit
{
    __shared__ float h_s[2][NB][160];
    __shared__ float a_s[4][80][NB];   // a_r, a_z, hn, xn
    __shared__ __align__(8) unsigned long long mbar_sto;

    const int tid  = threadIdx.x;
    const int rank = blockIdx.x & 1;
    const int c    = blockIdx.x >> 1;
    const int dir  = c & 1;
    const int b0   = (c >> 1) * NB;
    const int peer = rank ^ 1;

    const uint32_t mbar = (uint32_t)__cvta_generic_to_shared(&mbar_sto);
    uint32_t mbar_peer;
    asm volatile("mapa.shared::cluster.u32 %0, %1, %2;"
                 : "=r"(mbar_peer) : "r"(mbar), "r"(peer));

    const int gate = tid / 80;      // valid for tid < 240
    const int j    = tid % 80;
    const int grow = dir * 480 + gate * 160 + rank * 80 + j;

    // one-time preload of this thread's Whh row into registers
    float4 w4[40];
    float  bb = 0.f;
    if (tid < 240) {
        const float4* wp = reinterpret_cast<const float4*>(whh + (size_t)grow * 160);
#pragma unroll
        for (int kb = 0; kb < 40; kb++) w4[kb] = wp[kb];
        bb = bhh[grow];
    }

    for (int f = tid; f < 2 * NB * 160; f += blockDim.x)
        (&h_s[0][0][0])[f] = 0.f;
    if (tid == 0) {
        asm volatile("mbarrier.init.shared.b64 [%0], %1;" :: "r"(mbar), "r"(160u) : "memory");
    }
    __syncthreads();
    asm volatile("barrier.cluster.arrive.aligned;" ::: "memory");
    asm volatile("barrier.cluster.wait.aligned;" ::: "memory");

    const int xcol = dir * 480 + gate * 160 + rank * 80 + j;
    const int kloc = rank * 20;          // local-half k offset (float4 units)
    const int kpee = (rank ^ 1) * 20;    // peer-half k offset

    float xv[NB];
    {
        const int t0 = dir ? (T_SEQ - 1) : 0;
        if (tid < 240) {
#pragma unroll
            for (int b = 0; b < NB; b++)
                xv[b] = xw[((size_t)(b0 + b) * T_SEQ + t0) * 960 + xcol];
        }
    }

    int cur = 0;
    for (int s = 0; s < T_SEQ; s++) {
        const int t = dir ? (T_SEQ - 1 - s) : s;

        if (tid < 240) {
            float accum[NB];
#pragma unroll
            for (int b = 0; b < NB; b++) accum[b] = bb;
            const float4* hc0 = reinterpret_cast<const float4*>(&h_s[cur][0][0]);
            const float4* hc1 = reinterpret_cast<const float4*>(&h_s[cur][1][0]);

            // local-half FMAs (no dependency on the peer's arrival)
#pragma unroll
            for (int kb = 0; kb < 20; kb++) {
                float4 w  = w4[kloc + kb];
                float4 h0 = hc0[kloc + kb];
                float4 h1 = hc1[kloc + kb];
                accum[0] = fmaf(w.x, h0.x, accum[0]);
                accum[0] = fmaf(w.y, h0.y, accum[0]);
                accum[0] = fmaf(w.z, h0.z, accum[0]);
                accum[0] = fmaf(w.w, h0.w, accum[0]);
                accum[1] = fmaf(w.x, h1.x, accum[1]);
                accum[1] = fmaf(w.y, h1.y, accum[1]);
                accum[1] = fmaf(w.z, h1.z, accum[1]);
                accum[1] = fmaf(w.w, h1.w, accum[1]);
            }
            // wait for the peer's h-half from the previous step
            if (s > 0) mbar_wait_acq(mbar, (uint32_t)((s - 1) & 1));
            // peer-half FMAs
#pragma unroll
            for (int kb = 0; kb < 20; kb++) {
                float4 w  = w4[kpee + kb];
                float4 h0 = hc0[kpee + kb];
                float4 h1 = hc1[kpee + kb];
                accum[0] = fmaf(w.x, h0.x, accum[0]);
                accum[0] = fmaf(w.y, h0.y, accum[0]);
                accum[0] = fmaf(w.z, h0.z, accum[0]);
                accum[0] = fmaf(w.w, h0.w, accum[0]);
                accum[1] = fmaf(w.x, h1.x, accum[1]);
                accum[1] = fmaf(w.y, h1.y, accum[1]);
                accum[1] = fmaf(w.z, h1.z, accum[1]);
                accum[1] = fmaf(w.w, h1.w, accum[1]);
            }
#pragma unroll
            for (int b = 0; b < NB; b++) {
                if (gate == 0)      a_s[0][j][b] = xv[b] + accum[b];
                else if (gate == 1) a_s[1][j][b] = xv[b] + accum[b];
                else {              a_s[2][j][b] = accum[b];
                                    a_s[3][j][b] = xv[b]; }
            }
        }
        __syncthreads();

        if (tid < 80 * NB) {
            int jj = tid % 80;
            int b  = tid / 80;
            float ar = a_s[0][jj][b];
            float az = a_s[1][jj][b];
            float hn = a_s[2][jj][b];
            float xn = a_s[3][jj][b];
            float r = 1.f / (1.f + expf(-ar));
            float z = 1.f / (1.f + expf(-az));
            float n = tanhf(xn + r * hn);
            float hp = h_s[cur][b][rank * 80 + jj];
            float hnew = (1.f - z) * n + z * hp;
            int nxt = cur ^ 1;
            float* lp = &h_s[nxt][b][rank * 80 + jj];
            *lp = hnew;                                   // local copy
            uint32_t saddr = (uint32_t)__cvta_generic_to_shared(lp);
            uint32_t paddr;
            asm volatile("mapa.shared::cluster.u32 %0, %1, %2;"
                         : "=r"(paddr) : "r"(saddr), "r"(peer));
            asm volatile("st.shared::cluster.f32 [%0], %1;"
                         :: "r"(paddr), "f"(hnew) : "memory");
            // release-arrive on the PEER's barrier: orders this thread's
            // remote store before the peer's acquire-wait observes phase done.
            asm volatile("mbarrier.arrive.release.cluster.shared::cluster.b64 _, [%0];"
                         :: "r"(mbar_peer) : "memory");
            size_t tok = (size_t)(b0 + b) * T_SEQ + t;
            out[tok * 320 + dir * 160 + rank * 80 + jj] = hnew;
        }
        // prefetch next step's xW (overlaps the ewise phase of other threads)
        if (s + 1 < T_SEQ && tid < 240) {
            const int tn = dir ? (T_SEQ - 2 - s) : (s + 1);
#pragma unroll
            for (int b = 0; b < NB; b++)
                xv[b] = xw[((size_t)(b0 + b) * T_SEQ + tn) * 960 + xcol];
        }
        __syncthreads();
        cur ^= 1;
    }

    // do not exit while the peer may still write into our SMEM
    asm volatile("barrier.cluster.arrive.aligned;" ::: "memory");
    asm volatile("barrier.cluster.wait.aligned;" ::: "memory");
}

// ------------------------------ attention bits -----------------------------
__global__ void __launch_bounds__(256) logits_kernel(
    const float* __restrict__ keys, const float* __restrict__ sw,
    const float* __restrict__ sb, float* __restrict__ logits)
{
    int warp = (blockIdx.x * blockDim.x + threadIdx.x) >> 5;
    int lane = threadIdx.x & 31;
    if (warp >= NTOK) return;
    const float* kr = keys + (size_t)warp * 160;
    float a0 = 0.f, a1 = 0.f, a2 = 0.f, a3 = 0.f;
    for (int k = lane; k < 160; k += 32) {
        float kv = kr[k];
        a0 = fmaf(kv, sw[0 * 160 + k], a0);
        a1 = fmaf(kv, sw[1 * 160 + k], a1);
        a2 = fmaf(kv, sw[2 * 160 + k], a2);
        a3 = fmaf(kv, sw[3 * 160 + k], a3);
    }
#pragma unroll
    for (int off = 16; off; off >>= 1) {
        a0 += __shfl_xor_sync(0xffffffffu, a0, off);
        a1 += __shfl_xor_sync(0xffffffffu, a1, off);
        a2 += __shfl_xor_sync(0xffffffffu, a2, off);
        a3 += __shfl_xor_sync(0xffffffffu, a3, off);
    }
    if (lane == 0) {
        float* o = logits + (size_t)warp * 4;
        o[0] = a0 + sb[0]; o[1] = a1 + sb[1]; o[2] = a2 + sb[2]; o[3] = a3 + sb[3];
    }
}

__global__ void __launch_bounds__(512) motion_kernel(
    const float* __restrict__ x, float* __restrict__ motion)
{
    __shared__ float sd[512];
    __shared__ float red[512];
    int b = blockIdx.x, t = threadIdx.x;
    float d = 0.f;
    if (t >= 1) {
        const float4* r1 = reinterpret_cast<const float4*>(x + ((size_t)b * 512 + t) * 128);
        const float4* r0 = reinterpret_cast<const float4*>(x + ((size_t)b * 512 + t - 1) * 128);
        float acc = 0.f;
#pragma unroll 8
        for (int q = 0; q < 32; q++) {
            float4 a = r1[q], c = r0[q];
            float dx = a.x - c.x, dy = a.y - c.y, dz = a.z - c.z, dw = a.w - c.w;
            acc += dx * dx + dy * dy + dz * dz + dw * dw;
        }
        d = sqrtf(acc);
    }
    sd[t] = d;
    __syncthreads();
    if (t == 0) sd[0] = sd[1];
    __syncthreads();
    d = sd[t];
    red[t] = d; __syncthreads();
    for (int off = 256; off; off >>= 1) { if (t < off) red[t] += red[t + off]; __syncthreads(); }
    float mean = red[0] / 512.f;
    __syncthreads();
    float dd = d - mean;
    red[t] = dd * dd; __syncthreads();
    for (int off = 256; off; off >>= 1) { if (t < off) red[t] += red[t + off]; __syncthreads(); }
    float stdv = sqrtf(red[0] / 511.f);
    motion[(size_t)b * 512 + t] = (d - mean) / (stdv + 1e-6f);
}

__global__ void __launch_bounds__(512) softmax_kernel(
    const float* __restrict__ logits, const float* __restrict__ motion,
    float* __restrict__ wmean_out)
{
    __shared__ float4 red[512];
    int b = blockIdx.x, t = threadIdx.x;
    size_t tok = (size_t)b * 512 + t;
    float4 l = *reinterpret_cast<const float4*>(logits + tok * 4);
    float m = motion[tok];
    l.x += m; l.y += m; l.z += m; l.w += m;
    red[t] = l; __syncthreads();
    for (int off = 256; off; off >>= 1) {
        if (t < off) {
            float4 a = red[t], c = red[t + off];
            a.x = fmaxf(a.x, c.x); a.y = fmaxf(a.y, c.y);
            a.z = fmaxf(a.z, c.z); a.w = fmaxf(a.w, c.w);
            red[t] = a;
        }
        __syncthreads();
    }
    float4 mx = red[0];
    __syncthreads();
    float4 e;
    e.x = expf(l.x - mx.x); e.y = expf(l.y - mx.y);
    e.z = expf(l.z - mx.z); e.w = expf(l.w - mx.w);
    red[t] = e; __syncthreads();
    for (int off = 256; off; off >>= 1) {
        if (t < off) {
            float4 a = red[t], c = red[t + off];
            a.x += c.x; a.y += c.y; a.z += c.z; a.w += c.w;
            red[t] = a;
        }
        __syncthreads();
    }
    float4 s = red[0];
    wmean_out[tok] = 0.25f * (e.x / s.x + e.y / s.y + e.z / s.z + e.w / s.w);
}

__global__ void __launch_bounds__(320) pool_kernel(
    const float* __restrict__ seq, const float* __restrict__ wm,
    float* __restrict__ pooled)
{
    __shared__ float sw[512];
    int b = blockIdx.x, d = threadIdx.x;
    for (int i = d; i < 512; i += 320) sw[i] = wm[(size_t)b * 512 + i];
    __syncthreads();
    float acc = 0.f;
    const float* sp = seq + (size_t)b * 512 * 320 + d;
    for (int t = 0; t < 512; t++) acc = fmaf(sp[(size_t)t * 320], sw[t], acc);
    pooled[b * 320 + d] = acc;
}

__global__ void __launch_bounds__(256) final_kernel(
    const float* __restrict__ pooled, const float* __restrict__ pw,
    const float* __restrict__ pb, const float* __restrict__ lng,
    const float* __restrict__ lnb, float* __restrict__ out)
{
    __shared__ float sp[320];
    __shared__ float red[256];
    int b = blockIdx.x, e = threadIdx.x;
    for (int i = e; i < 320; i += 256) sp[i] = pooled[b * 320 + i];
    __syncthreads();
    float acc = 0.f;
    const float* wr = pw + (size_t)e * 320;
#pragma unroll 4
    for (int k = 0; k < 320; k += 4) {
        acc = fmaf(wr[k + 0], sp[k + 0], acc);
        acc = fmaf(wr[k + 1], sp[k + 1], acc);
        acc = fmaf(wr[k + 2], sp[k + 2], acc);
        acc = fmaf(wr[k + 3], sp[k + 3], acc);
    }
    acc += pb[e];
    red[e] = acc; __syncthreads();
    for (int off = 128; off; off >>= 1) { if (e < off) red[e] += red[e + off]; __syncthreads(); }
    float mean = red[0] / 256.f;
    __syncthreads();
    float dd = acc - mean;
    red[e] = dd * dd; __syncthreads();
    for (int off = 128; off; off >>= 1) { if (e < off) red[e] += red[e + off]; __syncthreads(); }
    float var = red[0] / 256.f;
    __syncthreads();
    float v = dd * rsqrtf(var + 1e-5f) * lng[e] + lnb[e];
    red[e] = v * v; __syncthreads();
    for (int off = 128; off; off >>= 1) { if (e < off) red[e] += red[e + off]; __syncthreads(); }
    float nrm = fmaxf(sqrtf(red[0]), 1e-12f);
    out[b * 256 + e] = v / nrm;
}

// ------------------------------- launch -------------------------------------
extern "C" void kernel_launch(void* const* d_in, const int* in_sizes, int n_in,
                              void* d_out, int out_size)
{
    const float* x       = (const float*)d_in[0];
    const float* Wih0    = (const float*)d_in[1];
    const float* Whh0    = (const float*)d_in[2];
    const float* bih0    = (const float*)d_in[3];
    const float* bhh0    = (const float*)d_in[4];
    const float* Wih1    = (const float*)d_in[5];
    const float* Whh1    = (const float*)d_in[6];
    const float* bih1    = (const float*)d_in[7];
    const float* bhh1    = (const float*)d_in[8];
    const float* key_w   = (const float*)d_in[9];
    const float* key_b   = (const float*)d_in[10];
    const float* score_w = (const float*)d_in[11];
    const float* score_b = (const float*)d_in[12];
    const float* proj_w  = (const float*)d_in[13];
    const float* proj_b  = (const float*)d_in[14];
    const float* ln_g    = (const float*)d_in[15];
    const float* ln_b    = (const float*)d_in[16];
    float* out = (float*)d_out;
    float* out_emb = out;            // (64, 256)
    float* out_wm  = out + 64 * 256; // (64, 512)

    float *xw, *h1, *seq, *keys, *logits, *motion, *pooled;
    cudaGetSymbolAddress((void**)&xw,     g_xw);
    cudaGetSymbolAddress((void**)&h1,     g_h1);
    cudaGetSymbolAddress((void**)&seq,    g_seq);
    cudaGetSymbolAddress((void**)&keys,   g_keys);
    cudaGetSymbolAddress((void**)&logits, g_logits);
    cudaGetSymbolAddress((void**)&motion, g_motion);
    cudaGetSymbolAddress((void**)&pooled, g_pooled);

    // motion is independent of the GRU chain
    motion_kernel<<<BATCH, 512>>>(x, motion);

    // layer 0
    sgemm_bias<<<dim3((960 + BN - 1) / BN, NTOK / BM), 256>>>(x, Wih0, bih0, xw, NTOK, 960, 128, 0);
    gru_layer<<<128, 256>>>(xw, Whh0, bhh0, h1);

    // layer 1
    sgemm_bias<<<dim3((960 + BN - 1) / BN, NTOK / BM), 256>>>(h1, Wih1, bih1, xw, NTOK, 960, 320, 0);
    gru_layer<<<128, 256>>>(xw, Whh1, bhh1, seq);

    // keys = tanh(seq @ key_w^T + key_b)
    sgemm_bias<<<dim3((160 + BN - 1) / BN, NTOK / BM), 256>>>(seq, key_w, key_b, keys, NTOK, 160, 320, 1);

    // attention logits, softmax over T (writes weights.mean to out_wm)
    logits_kernel<<<NTOK / 8, 256>>>(keys, score_w, score_b, logits);
    softmax_kernel<<<BATCH, 512>>>(logits, motion, out_wm);

    // pooled + projection + LN + L2 norm
    pool_kernel<<<BATCH, 320>>>(seq, out_wm, pooled);
    final_kernel<<<BATCH, 256>>>(pooled, proj_w, proj_b, ln_g, ln_b, out_emb);
}

// round 6
// speedup vs baseline: 1.4160x; 1.4160x over previous
#include <cuda_runtime.h>
#include <cuda_bf16.h>
#include <cstdint>
#include <cstddef>

#define T_SEQ 512
#define BATCH 64
#define NTOK  (BATCH * T_SEQ)   // 32768
#define NB 2                    // batches per GRU cluster

typedef unsigned long long ull;

// ---- packed f32x2 helpers (sm_103a FFMA2 path) -----------------------------
__device__ __forceinline__ void fma2(ull& d, ull a, ull b) {
    asm("fma.rn.f32x2 %0, %1, %2, %0;" : "+l"(d) : "l"(a), "l"(b));
}
__device__ __forceinline__ ull pk2(float lo, float hi) {
    ull d; asm("mov.b64 %0, {%1, %2};" : "=l"(d) : "f"(lo), "f"(hi)); return d;
}
__device__ __forceinline__ float2 upk2(ull v) {
    float2 r; asm("mov.b64 {%0, %1}, %2;" : "=f"(r.x), "=f"(r.y) : "l"(v)); return r;
}

// ----------------------------- scratch ------------------------------------
__device__ float g_xw[(size_t)NTOK * 960];
__device__ float g_h1[(size_t)NTOK * 320];
__device__ float g_seq[(size_t)NTOK * 320];
__device__ float g_keys[(size_t)NTOK * 160];
__device__ float g_logits[(size_t)NTOK * 4];
__device__ float g_motion[NTOK];
__device__ float g_pooled[BATCH * 320];

// ----------------------- SGEMM: C = A(MxK) * B(NxK)^T + bias ---------------
#define BM 128
#define BN 128
#define BK 16

__global__ void __launch_bounds__(256) sgemm_bias(
    const float* __restrict__ A, const float* __restrict__ B,
    const float* __restrict__ bias, float* __restrict__ C,
    int M, int N, int K, int act)
{
    __shared__ __align__(16) float As[BK][BM + 4];
    __shared__ __align__(16) float Bs[BK][BN + 4];

    const int tid = threadIdx.x;
    const int tx = tid & 15;
    const int ty = tid >> 4;
    const int bm = blockIdx.y * BM;
    const int bn = blockIdx.x * BN;

    ull acc2[8][4];
#pragma unroll
    for (int i = 0; i < 8; i++)
#pragma unroll
        for (int j = 0; j < 4; j++) acc2[i][j] = 0ull;

    const int ntiles = K / BK;
    for (int kt = 0; kt < ntiles; kt++) {
        const int k0 = kt * BK;
#pragma unroll
        for (int i = 0; i < 2; i++) {
            int f = tid * 2 + i;
            int r = f >> 2, c = f & 3;
            float4 v = *reinterpret_cast<const float4*>(A + (size_t)(bm + r) * K + k0 + c * 4);
            As[c * 4 + 0][r] = v.x; As[c * 4 + 1][r] = v.y;
            As[c * 4 + 2][r] = v.z; As[c * 4 + 3][r] = v.w;
        }
#pragma unroll
        for (int i = 0; i < 2; i++) {
            int f = tid * 2 + i;
            int r = f >> 2, c = f & 3;
            float4 v = make_float4(0.f, 0.f, 0.f, 0.f);
            if (bn + r < N)
                v = *reinterpret_cast<const float4*>(B + (size_t)(bn + r) * K + k0 + c * 4);
            Bs[c * 4 + 0][r] = v.x; Bs[c * 4 + 1][r] = v.y;
            Bs[c * 4 + 2][r] = v.z; Bs[c * 4 + 3][r] = v.w;
        }
        __syncthreads();
#pragma unroll
        for (int kk = 0; kk < BK; kk++) {
            float4 a0 = *reinterpret_cast<const float4*>(&As[kk][ty * 8]);
            float4 a1 = *reinterpret_cast<const float4*>(&As[kk][ty * 8 + 4]);
            ulonglong2 B0 = *reinterpret_cast<const ulonglong2*>(&Bs[kk][tx * 8]);
            ulonglong2 B1 = *reinterpret_cast<const ulonglong2*>(&Bs[kk][tx * 8 + 4]);
            float av[8] = {a0.x, a0.y, a0.z, a0.w, a1.x, a1.y, a1.z, a1.w};
#pragma unroll
            for (int i = 0; i < 8; i++) {
                ull ap = pk2(av[i], av[i]);
                fma2(acc2[i][0], ap, B0.x);
                fma2(acc2[i][1], ap, B0.y);
                fma2(acc2[i][2], ap, B1.x);
                fma2(acc2[i][3], ap, B1.y);
            }
        }
        __syncthreads();
    }
#pragma unroll
    for (int i = 0; i < 8; i++) {
        size_t row = (size_t)(bm + ty * 8 + i);
#pragma unroll
        for (int jp = 0; jp < 4; jp++) {
            float2 cc = upk2(acc2[i][jp]);
            int col = bn + tx * 8 + jp * 2;
            if (col < N) {
                float v = cc.x + bias[col];
                if (act) v = tanhf(v);
                C[row * N + col] = v;
            }
            if (col + 1 < N) {
                float v = cc.y + bias[col + 1];
                if (act) v = tanhf(v);
                C[row * N + col + 1] = v;
            }
        }
    }
}

// --------------------------- GRU layer (2-CTA cluster) ---------------------
// 128 CTAs = 64 clusters. cluster c = blockIdx.x>>1: dir = c&1, batch group
// = c>>1 (NB batches). rank = blockIdx.x&1 owns hidden units [rank*80,+80).
// Whh rows live in REGISTERS as packed f32x2; h read via LDS.128 -> ulonglong2.
__global__ void __cluster_dims__(2, 1, 1) __launch_bounds__(256, 1) gru_layer(
    const float* __restrict__ xw,    // (NTOK, 960): col = dir*480 + gate*160 + unit
    const float* __restrict__ whh,   // (2, 480, 160)
    const float* __restrict__ bhh,   // (2, 480)
    float* __restrict__ out)         // (NTOK, 320): col = dir*160 + unit
{
    __shared__ __align__(16) float h_s[2][NB][160];
    __shared__ float a_s[4][80][NB];   // a_r, a_z, hn, xn

    const int tid  = threadIdx.x;
    const int rank = blockIdx.x & 1;
    const int c    = blockIdx.x >> 1;
    const int dir  = c & 1;
    const int b0   = (c >> 1) * NB;
    const int peer = rank ^ 1;

    const int gate = tid / 80;      // valid for tid < 240
    const int j    = tid % 80;
    const int grow = dir * 480 + gate * 160 + rank * 80 + j;

    // one-time preload of this thread's Whh row into PACKED registers
    ull wp[80];
    float bb = 0.f;
    if (tid < 240) {
        const float4* wq = reinterpret_cast<const float4*>(whh + (size_t)grow * 160);
#pragma unroll
        for (int kb = 0; kb < 40; kb++) {
            float4 v = wq[kb];
            wp[2 * kb]     = pk2(v.x, v.y);
            wp[2 * kb + 1] = pk2(v.z, v.w);
        }
        bb = bhh[grow];
    }

    for (int f = tid; f < 2 * NB * 160; f += blockDim.x)
        (&h_s[0][0][0])[f] = 0.f;
    __syncthreads();
    asm volatile("barrier.cluster.arrive.aligned;" ::: "memory");
    asm volatile("barrier.cluster.wait.aligned;" ::: "memory");

    const int xcol = dir * 480 + gate * 160 + rank * 80 + j;

    // preload xW for step 0
    float xv[NB];
    {
        const int t0 = dir ? (T_SEQ - 1) : 0;
        if (tid < 240) {
#pragma unroll
            for (int b = 0; b < NB; b++)
                xv[b] = xw[((size_t)(b0 + b) * T_SEQ + t0) * 960 + xcol];
        }
    }

    int cur = 0;
    for (int s = 0; s < T_SEQ; s++) {
        const int t = dir ? (T_SEQ - 1 - s) : s;

        if (tid < 240) {
            ull c0a = 0ull, c0b = 0ull, c1a = 0ull, c1b = 0ull;
            const ulonglong2* hq0 = reinterpret_cast<const ulonglong2*>(&h_s[cur][0][0]);
            const ulonglong2* hq1 = reinterpret_cast<const ulonglong2*>(&h_s[cur][1][0]);
#pragma unroll
            for (int kb = 0; kb < 40; kb++) {
                ulonglong2 H0 = hq0[kb];   // broadcast LDS.128 -> 2 packed pairs
                ulonglong2 H1 = hq1[kb];
                fma2(c0a, wp[2 * kb],     H0.x);
                fma2(c0b, wp[2 * kb + 1], H0.y);
                fma2(c1a, wp[2 * kb],     H1.x);
                fma2(c1b, wp[2 * kb + 1], H1.y);
            }
            float2 p0 = upk2(c0a), q0 = upk2(c0b);
            float2 p1 = upk2(c1a), q1 = upk2(c1b);
            float accum0 = bb + ((p0.x + p0.y) + (q0.x + q0.y));
            float accum1 = bb + ((p1.x + p1.y) + (q1.x + q1.y));

            if (gate == 0)      { a_s[0][j][0] = xv[0] + accum0; a_s[0][j][1] = xv[1] + accum1; }
            else if (gate == 1) { a_s[1][j][0] = xv[0] + accum0; a_s[1][j][1] = xv[1] + accum1; }
            else {              a_s[2][j][0] = accum0;  a_s[2][j][1] = accum1;
                                a_s[3][j][0] = xv[0];   a_s[3][j][1] = xv[1]; }
        }
        __syncthreads();

        if (tid < 80 * NB) {
            int jj = tid % 80;
            int b  = tid / 80;
            float ar = a_s[0][jj][b];
            float az = a_s[1][jj][b];
            float hn = a_s[2][jj][b];
            float xn = a_s[3][jj][b];
            float r = 1.f / (1.f + expf(-ar));
            float z = 1.f / (1.f + expf(-az));
            float n = tanhf(xn + r * hn);
            float hp = h_s[cur][b][rank * 80 + jj];
            float hnew = (1.f - z) * n + z * hp;
            int nxt = cur ^ 1;
            float* lp = &h_s[nxt][b][rank * 80 + jj];
            *lp = hnew;                                   // local half
            uint32_t saddr = (uint32_t)__cvta_generic_to_shared(lp);
            uint32_t paddr;
            asm volatile("mapa.shared::cluster.u32 %0, %1, %2;"
                         : "=r"(paddr) : "r"(saddr), "r"(peer));
            asm volatile("st.shared::cluster.f32 [%0], %1;"
                         :: "r"(paddr), "f"(hnew) : "memory");
            size_t tok = (size_t)(b0 + b) * T_SEQ + t;
            out[tok * 320 + dir * 160 + rank * 80 + jj] = hnew;
        }
        asm volatile("barrier.cluster.arrive.aligned;" ::: "memory");

        // hide next step's xW gather behind the cluster barrier
        if (s + 1 < T_SEQ && tid < 240) {
            const int tn = dir ? (T_SEQ - 2 - s) : (s + 1);
#pragma unroll
            for (int b = 0; b < NB; b++)
                xv[b] = xw[((size_t)(b0 + b) * T_SEQ + tn) * 960 + xcol];
        }
        asm volatile("barrier.cluster.wait.aligned;" ::: "memory");
        cur ^= 1;
    }
}

// ------------------------------ attention bits -----------------------------
__global__ void __launch_bounds__(256) logits_kernel(
    const float* __restrict__ keys, const float* __restrict__ sw,
    const float* __restrict__ sb, float* __restrict__ logits)
{
    int warp = (blockIdx.x * blockDim.x + threadIdx.x) >> 5;
    int lane = threadIdx.x & 31;
    if (warp >= NTOK) return;
    const float* kr = keys + (size_t)warp * 160;
    float a0 = 0.f, a1 = 0.f, a2 = 0.f, a3 = 0.f;
    for (int k = lane; k < 160; k += 32) {
        float kv = kr[k];
        a0 = fmaf(kv, sw[0 * 160 + k], a0);
        a1 = fmaf(kv, sw[1 * 160 + k], a1);
        a2 = fmaf(kv, sw[2 * 160 + k], a2);
        a3 = fmaf(kv, sw[3 * 160 + k], a3);
    }
#pragma unroll
    for (int off = 16; off; off >>= 1) {
        a0 += __shfl_xor_sync(0xffffffffu, a0, off);
        a1 += __shfl_xor_sync(0xffffffffu, a1, off);
        a2 += __shfl_xor_sync(0xffffffffu, a2, off);
        a3 += __shfl_xor_sync(0xffffffffu, a3, off);
    }
    if (lane == 0) {
        float* o = logits + (size_t)warp * 4;
        o[0] = a0 + sb[0]; o[1] = a1 + sb[1]; o[2] = a2 + sb[2]; o[3] = a3 + sb[3];
    }
}

__global__ void __launch_bounds__(512) motion_kernel(
    const float* __restrict__ x, float* __restrict__ motion)
{
    __shared__ float sd[512];
    __shared__ float red[512];
    int b = blockIdx.x, t = threadIdx.x;
    float d = 0.f;
    if (t >= 1) {
        const float4* r1 = reinterpret_cast<const float4*>(x + ((size_t)b * 512 + t) * 128);
        const float4* r0 = reinterpret_cast<const float4*>(x + ((size_t)b * 512 + t - 1) * 128);
        float acc = 0.f;
#pragma unroll 8
        for (int q = 0; q < 32; q++) {
            float4 a = r1[q], c = r0[q];
            float dx = a.x - c.x, dy = a.y - c.y, dz = a.z - c.z, dw = a.w - c.w;
            acc += dx * dx + dy * dy + dz * dz + dw * dw;
        }
        d = sqrtf(acc);
    }
    sd[t] = d;
    __syncthreads();
    if (t == 0) sd[0] = sd[1];
    __syncthreads();
    d = sd[t];
    red[t] = d; __syncthreads();
    for (int off = 256; off; off >>= 1) { if (t < off) red[t] += red[t + off]; __syncthreads(); }
    float mean = red[0] / 512.f;
    __syncthreads();
    float dd = d - mean;
    red[t] = dd * dd; __syncthreads();
    for (int off = 256; off; off >>= 1) { if (t < off) red[t] += red[t + off]; __syncthreads(); }
    float stdv = sqrtf(red[0] / 511.f);
    motion[(size_t)b * 512 + t] = (d - mean) / (stdv + 1e-6f);
}

__global__ void __launch_bounds__(512) softmax_kernel(
    const float* __restrict__ logits, const float* __restrict__ motion,
    float* __restrict__ wmean_out)
{
    __shared__ float4 red[512];
    int b = blockIdx.x, t = threadIdx.x;
    size_t tok = (size_t)b * 512 + t;
    float4 l = *reinterpret_cast<const float4*>(logits + tok * 4);
    float m = motion[tok];
    l.x += m; l.y += m; l.z += m; l.w += m;
    red[t] = l; __syncthreads();
    for (int off = 256; off; off >>= 1) {
        if (t < off) {
            float4 a = red[t], c = red[t + off];
            a.x = fmaxf(a.x, c.x); a.y = fmaxf(a.y, c.y);
            a.z = fmaxf(a.z, c.z); a.w = fmaxf(a.w, c.w);
            red[t] = a;
        }
        __syncthreads();
    }
    float4 mx = red[0];
    __syncthreads();
    float4 e;
    e.x = expf(l.x - mx.x); e.y = expf(l.y - mx.y);
    e.z = expf(l.z - mx.z); e.w = expf(l.w - mx.w);
    red[t] = e; __syncthreads();
    for (int off = 256; off; off >>= 1) {
        if (t < off) {
            float4 a = red[t], c = red[t + off];
            a.x += c.x; a.y += c.y; a.z += c.z; a.w += c.w;
            red[t] = a;
        }
        __syncthreads();
    }
    float4 s = red[0];
    wmean_out[tok] = 0.25f * (e.x / s.x + e.y / s.y + e.z / s.z + e.w / s.w);
}

__global__ void __launch_bounds__(320) pool_kernel(
    const float* __restrict__ seq, const float* __restrict__ wm,
    float* __restrict__ pooled)
{
    __shared__ float sw[512];
    int b = blockIdx.x, d = threadIdx.x;
    for (int i = d; i < 512; i += 320) sw[i] = wm[(size_t)b * 512 + i];
    __syncthreads();
    float acc = 0.f;
    const float* sp = seq + (size_t)b * 512 * 320 + d;
    for (int t = 0; t < 512; t++) acc = fmaf(sp[(size_t)t * 320], sw[t], acc);
    pooled[b * 320 + d] = acc;
}

__global__ void __launch_bounds__(256) final_kernel(
    const float* __restrict__ pooled, const float* __restrict__ pw,
    const float* __restrict__ pb, const float* __restrict__ lng,
    const float* __restrict__ lnb, float* __restrict__ out)
{
    __shared__ float sp[320];
    __shared__ float red[256];
    int b = blockIdx.x, e = threadIdx.x;
    for (int i = e; i < 320; i += 256) sp[i] = pooled[b * 320 + i];
    __syncthreads();
    float acc = 0.f;
    const float* wr = pw + (size_t)e * 320;
#pragma unroll 4
    for (int k = 0; k < 320; k += 4) {
        acc = fmaf(wr[k + 0], sp[k + 0], acc);
        acc = fmaf(wr[k + 1], sp[k + 1], acc);
        acc = fmaf(wr[k + 2], sp[k + 2], acc);
        acc = fmaf(wr[k + 3], sp[k + 3], acc);
    }
    acc += pb[e];
    red[e] = acc; __syncthreads();
    for (int off = 128; off; off >>= 1) { if (e < off) red[e] += red[e + off]; __syncthreads(); }
    float mean = red[0] / 256.f;
    __syncthreads();
    float dd = acc - mean;
    red[e] = dd * dd; __syncthreads();
    for (int off = 128; off; off >>= 1) { if (e < off) red[e] += red[e + off]; __syncthreads(); }
    float var = red[0] / 256.f;
    __syncthreads();
    float v = dd * rsqrtf(var + 1e-5f) * lng[e] + lnb[e];
    red[e] = v * v; __syncthreads();
    for (int off = 128; off; off >>= 1) { if (e < off) red[e] += red[e + off]; __syncthreads(); }
    float nrm = fmaxf(sqrtf(red[0]), 1e-12f);
    out[b * 256 + e] = v / nrm;
}

// ------------------------------- launch -------------------------------------
extern "C" void kernel_launch(void* const* d_in, const int* in_sizes, int n_in,
                              void* d_out, int out_size)
{
    const float* x       = (const float*)d_in[0];
    const float* Wih0    = (const float*)d_in[1];
    const float* Whh0    = (const float*)d_in[2];
    const float* bih0    = (const float*)d_in[3];
    const float* bhh0    = (const float*)d_in[4];
    const float* Wih1    = (const float*)d_in[5];
    const float* Whh1    = (const float*)d_in[6];
    const float* bih1    = (const float*)d_in[7];
    const float* bhh1    = (const float*)d_in[8];
    const float* key_w   = (const float*)d_in[9];
    const float* key_b   = (const float*)d_in[10];
    const float* score_w = (const float*)d_in[11];
    const float* score_b = (const float*)d_in[12];
    const float* proj_w  = (const float*)d_in[13];
    const float* proj_b  = (const float*)d_in[14];
    const float* ln_g    = (const float*)d_in[15];
    const float* ln_b    = (const float*)d_in[16];
    float* out = (float*)d_out;
    float* out_emb = out;            // (64, 256)
    float* out_wm  = out + 64 * 256; // (64, 512)

    float *xw, *h1, *seq, *keys, *logits, *motion, *pooled;
    cudaGetSymbolAddress((void**)&xw,     g_xw);
    cudaGetSymbolAddress((void**)&h1,     g_h1);
    cudaGetSymbolAddress((void**)&seq,    g_seq);
    cudaGetSymbolAddress((void**)&keys,   g_keys);
    cudaGetSymbolAddress((void**)&logits, g_logits);
    cudaGetSymbolAddress((void**)&motion, g_motion);
    cudaGetSymbolAddress((void**)&pooled, g_pooled);

    // motion is independent of the GRU chain
    motion_kernel<<<BATCH, 512>>>(x, motion);

    // layer 0
    sgemm_bias<<<dim3((960 + BN - 1) / BN, NTOK / BM), 256>>>(x, Wih0, bih0, xw, NTOK, 960, 128, 0);
    gru_layer<<<128, 256>>>(xw, Whh0, bhh0, h1);

    // layer 1
    sgemm_bias<<<dim3((960 + BN - 1) / BN, NTOK / BM), 256>>>(h1, Wih1, bih1, xw, NTOK, 960, 320, 0);
    gru_layer<<<128, 256>>>(xw, Whh1, bhh1, seq);

    // keys = tanh(seq @ key_w^T + key_b)
    sgemm_bias<<<dim3((160 + BN - 1) / BN, NTOK / BM), 256>>>(seq, key_w, key_b, keys, NTOK, 160, 320, 1);

    // attention logits, softmax over T (writes weights.mean to out_wm)
    logits_kernel<<<NTOK / 8, 256>>>(keys, score_w, score_b, logits);
    softmax_kernel<<<BATCH, 512>>>(logits, motion, out_wm);

    // pooled + projection + LN + L2 norm
    pool_kernel<<<BATCH, 320>>>(seq, out_wm, pooled);
    final_kernel<<<BATCH, 256>>>(pooled, proj_w, proj_b, ln_g, ln_b, out_emb);
}